// round 8
// baseline (speedup 1.0000x reference)
#include <cuda_runtime.h>
#include <cuda_bf16.h>

#define Bsz   256
#define Tsz   512
#define Tpad  520               // padded time axis: ring refresh never clamps
#define Csz   128
#define Lsz   64
#define BLANKC 127
#define PF    8
#define LN2f  0.69314718055994530942f
#define ESENT (-(1 << 29))

// probabilities, precomputed by kernel 1:
//   g_p2[b][t][j] = softmax prob of label j (j = 0..63), laid out so lane l's
//   float2 (labels 2l, 2l+1) is contiguous; g_pb[b][t] = blank prob.
__device__ float2 g_p2[(size_t)Bsz * Tpad * 32];
__device__ float  g_pb[(size_t)Bsz * Tpad];

// ---------------------------------------------------------------------------
// Kernel 1: softmax per (b,t) row + gather label/blank probs.
// One warp per row (4 rows / 128-thread block). No block barriers.
// ---------------------------------------------------------------------------
__global__ __launch_bounds__(128)
void ctc_probs(const float* __restrict__ y_pred,
               const int*   __restrict__ y_true) {
    const int row  = blockIdx.x * 4 + (threadIdx.x >> 5);   // row = b*512 + t
    const int lane = threadIdx.x & 31;
    const int wid  = (threadIdx.x >> 5);

    __shared__ float sh[4][128];

    const float4 v = reinterpret_cast<const float4*>(y_pred + (size_t)row * Csz)[lane];
    float m = fmaxf(fmaxf(v.x, v.y), fmaxf(v.z, v.w));
    #pragma unroll
    for (int o = 16; o; o >>= 1) m = fmaxf(m, __shfl_xor_sync(0xffffffffu, m, o));

    const float ex = __expf(v.x - m), ey = __expf(v.y - m),
                ez = __expf(v.z - m), ew = __expf(v.w - m);
    float esum = (ex + ey) + (ez + ew);
    #pragma unroll
    for (int o = 16; o; o >>= 1) esum += __shfl_xor_sync(0xffffffffu, esum, o);
    const float inv = __frcp_rn(esum);

    reinterpret_cast<float4*>(sh[wid])[lane] = make_float4(ex, ey, ez, ew);
    __syncwarp();

    const int b = row >> 9;          // Tsz = 512
    const int t = row & 511;
    const int* yt = y_true + b * Lsz;
    const int z1 = yt[2 * lane];
    const int z3 = yt[2 * lane + 1];

    g_p2[((size_t)b * Tpad + t) * 32 + lane] =
        make_float2(sh[wid][z1] * inv, sh[wid][z3] * inv);
    if (lane == 0) g_pb[(size_t)b * Tpad + t] = sh[wid][BLANKC] * inv;
}

// exact 2^d for d <= 0 (relative to max): clamps to exactly 0 beyond -127
__device__ __forceinline__ float w2i(int d) {
    return __int_as_float(max(d + 127, 0) << 23);
}
// renormalize v carrying exponent E -> mant in [1,2), int exp
__device__ __forceinline__ void norm2(float v, int E, float& m, int& e) {
    const int vb = __float_as_int(v);
    m = __int_as_float((vb & 0x007FFFFF) | 0x3F800000);
    e = E + (vb >> 23) - 127;
}

// ---------------------------------------------------------------------------
// Kernel 2: warp-per-batch-row alpha recurrence, 4 rows per CTA so the four
// warps land on four DIFFERENT SMSPs (R7 ran all warps on SMSP 0).
// Lane l owns states 4l..4l+3 (+state 128 logical on lane 31). Only cross-lane
// dep per step: old state 4l-1 -> 2 shfl_up. Linear domain, per-state int exp.
// No MUFU on the chain; probs come from the L2-resident precomputed arrays.
// ---------------------------------------------------------------------------
__global__ __launch_bounds__(128)
void ctc_alpha(const int* __restrict__ y_true,
               const int* __restrict__ input_length,
               const int* __restrict__ label_length,
               float*     __restrict__ out) {
    const int b = blockIdx.x * 4 + (threadIdx.x >> 5);
    const int l = threadIdx.x & 31;
    const int wid = threadIdx.x >> 5;

    const int z1 = y_true[b * Lsz + 2 * l];
    const bool skip1 = (4 * l + 1 >= 3) &&
                       (z1 != y_true[b * Lsz + max(2 * l - 1, 0)]);
    const bool skip3 = (y_true[b * Lsz + 2 * l + 1] != z1);
    const int T_run = input_length[b];

    const float2* pp  = g_p2 + (size_t)b * Tpad * 32 + l;   // stride 32 per t
    const float*  pbp = g_pb + (size_t)b * Tpad;

    float m0 = 0.f, m1 = 0.f, m2 = 0.f, m3 = 0.f, m4 = 0.f;
    int   e0 = ESENT, e1 = ESENT, e2 = ESENT, e3 = ESENT, e4 = ESENT;

    if (l == 0) {                        // t = 0 init (states 0 and 1)
        const float2 q = pp[0];
        norm2(pbp[0], 0, m0, e0);
        norm2(q.x,    0, m1, e1);
    }

    // prefetch rings for t = 1..PF (compile-time indices; pad => no clamps)
    float2 xr[PF]; float pr[PF];
    #pragma unroll
    for (int i = 0; i < PF; ++i) {
        xr[i] = pp[(size_t)(1 + i) * 32];
        pr[i] = pbp[1 + i];
    }

#define STEP(tc, j) {                                                         \
    const float p1 = xr[j].x, p3 = xr[j].y, pb = pr[j];                       \
    xr[j] = pp[(size_t)((tc) + PF) * 32];                                     \
    pr[j] = pbp[(tc) + PF];                                                   \
    float mN = __shfl_up_sync(0xffffffffu, m3, 1);                            \
    int   eN = __shfl_up_sync(0xffffffffu, e3, 1);                            \
    if (l == 0) { eN = ESENT; mN = 0.f; }                                     \
    float nm0, nm1, nm2, nm3, nm4; int ne0, ne1, ne2, ne3, ne4;               \
    { const int E = max(e0, eN);                                              \
      norm2((fmaf(mN, w2i(eN - E), m0 * w2i(e0 - E))) * pb, E, nm0, ne0); }   \
    { const int ec = skip1 ? eN : ESENT;                                      \
      const int E = max(e1, max(e0, ec));                                     \
      float v = fmaf(m0, w2i(e0 - E), m1 * w2i(e1 - E));                      \
      v = fmaf(mN, w2i(ec - E), v) * p1;                                      \
      norm2(v, E, nm1, ne1); }                                                \
    { const int E = max(e2, e1);                                              \
      norm2((fmaf(m1, w2i(e1 - E), m2 * w2i(e2 - E))) * pb, E, nm2, ne2); }   \
    { const int ec = skip3 ? e1 : ESENT;                                      \
      const int E = max(e3, max(e2, ec));                                     \
      float v = fmaf(m2, w2i(e2 - E), m3 * w2i(e3 - E));                      \
      v = fmaf(m1, w2i(ec - E), v) * p3;                                      \
      norm2(v, E, nm3, ne3); }                                                \
    { const int E = max(e4, e3);                                              \
      norm2((fmaf(m3, w2i(e3 - E), m4 * w2i(e4 - E))) * pb, E, nm4, ne4); }   \
    m0 = nm0; e0 = ne0; m1 = nm1; e1 = ne1; m2 = nm2; e2 = ne2;               \
    m3 = nm3; e3 = ne3; m4 = nm4; e4 = ne4; }

    const int nsteps = T_run - 1;       // steps t = 1 .. T_run-1
    const int nfull  = nsteps >> 3;     // PF = 8
    const int rem    = nsteps & 7;

    int t = 1;
    for (int c = 0; c < nfull; ++c) {   // branch-free steady state
        #pragma unroll
        for (int j = 0; j < PF; ++j) STEP(t + j, j)
        t += PF;
    }
    #pragma unroll
    for (int j = 0; j < PF; ++j) {      // epilogue: warp-uniform guards
        if (j < rem) STEP(t + j, j)
    }
#undef STEP

    __shared__ float2 sh[4][130];
    sh[wid][4 * l + 0] = make_float2(m0, __int_as_float(e0));
    sh[wid][4 * l + 1] = make_float2(m1, __int_as_float(e1));
    sh[wid][4 * l + 2] = make_float2(m2, __int_as_float(e2));
    sh[wid][4 * l + 3] = make_float2(m3, __int_as_float(e3));
    if (l == 31) sh[wid][128] = make_float2(m4, __int_as_float(e4));
    __syncwarp();

    if (l == 0) {
        const int ll = label_length[b];
        const float2 u = sh[wid][2 * ll];
        const float2 v = sh[wid][2 * ll - 1];
        const int eu = __float_as_int(u.y);
        const int ev = __float_as_int(v.y);
        const int Em = max(eu, ev);
        const float sum = u.x * w2i(eu - Em) + v.x * w2i(ev - Em);
        out[b] = -(__logf(sum) + (float)Em * LN2f);
    }
}

// ---------------------------------------------------------------------------
extern "C" void kernel_launch(void* const* d_in, const int* in_sizes, int n_in,
                              void* d_out, int out_size) {
    const int*   y_true = nullptr;
    const float* y_pred = nullptr;
    const int*   ilen   = nullptr;
    const int*   llen   = nullptr;
    for (int i = 0; i < n_in; ++i) {
        const int sz = in_sizes[i];
        if (sz == Bsz * Tsz * Csz)      y_pred = (const float*)d_in[i];
        else if (sz == Bsz * Lsz)       y_true = (const int*)d_in[i];
        else if (sz == Bsz) {
            if (!ilen) ilen = (const int*)d_in[i];
            else       llen = (const int*)d_in[i];
        }
    }
    float* out = (float*)d_out;

    ctc_probs<<<(Bsz * Tsz) / 4, 128>>>(y_pred, y_true);
    ctc_alpha<<<Bsz / 4, 128>>>(y_true, ilen, llen, out);
}